// round 12
// baseline (speedup 1.0000x reference)
#include <cuda_runtime.h>
#include <math.h>

// Shapes fixed by reference: [2,4,32,64,64]
constexpr int Cc    = 32;          // channels
constexpr int HW    = 4096;        // 64*64 positions
constexpr int NI    = 8;           // B*L items
constexpr int TP    = 32;          // positions per tile
constexpr int NT    = 4;           // tiles per block (pipelined)
constexpr int BPI   = 32;          // blocks per item -> 256 blocks
constexpr int PITCH = 36;          // 9 x 16B rows; PITCH % 32 == 4 (bank-safe)
constexpr int TH1   = 192;         // 3 mats x 2 teams x 32 patches
constexpr int NREP  = 2;           // atomic accumulator replicas

// Replicated accumulators: [replica][item][mat][32*32]. Zero at module load;
// k_final re-zeroes after reading so every graph replay starts clean.
__device__ float g_acc[(size_t)NREP * NI * 3 * 1024];

// Physical row for logical channel c.  sigma(c) = ((c&3)<<3)|(c>>2).
// Conflict-free u64 LDS for both main-loop patterns (see r11 analysis).
__device__ __forceinline__ int rowmap(int c) { return ((c & 3) << 3) | (c >> 2); }

__device__ __forceinline__ void cp16(void* sm, const void* gm) {
    unsigned sa = (unsigned)__cvta_generic_to_shared(sm);
    asm volatile("cp.async.cg.shared.global [%0], [%1], 16;" :: "r"(sa), "l"(gm) : "memory");
}

__global__ __launch_bounds__(TH1, 2) void k_partial(const float* __restrict__ S,
                                                    const float* __restrict__ T,
                                                    float* __restrict__ out) {
    __shared__ __align__(16) float sS[2][Cc * PITCH];
    __shared__ __align__(16) float sT[2][Cc * PITCH];
    __shared__ __align__(16) float ivS[2][TP];
    __shared__ __align__(16) float ivT[2][TP];

    const int n   = blockIdx.y;
    const int w   = blockIdx.x;          // 0..31 within item
    const int tid = threadIdx.x;
    const int pbase = w * (NT * TP);

    if (w == 0 && n == 0 && tid == 0) *out = 0.f;   // graph edge orders before k_final

    const float* __restrict__ Sb = S + (size_t)n * Cc * HW;
    const float* __restrict__ Tb = T + (size_t)n * Cc * HW;

    // Load slots: 512 16B chunks per tile (2 tensors x 32 ch x 8 quads).
    // slot s: tensor=s>>8, c=(s>>3)&31, q=s&7. Threads own s = tid, tid+192, tid+384.
    auto issue_tile = [&](int buf, int k) {
#pragma unroll
        for (int s = tid; s < 512; s += TH1) {
            const int tensor = s >> 8, c = (s >> 3) & 31, q = s & 7;
            const float* g = (tensor ? Tb : Sb) + (size_t)c * HW + (pbase + k * TP) + 4 * q;
            float* sm = (tensor ? sT[buf] : sS[buf]) + rowmap(c) * PITCH + 4 * q;
            cp16(sm, g);
        }
        asm volatile("cp.async.commit_group;" ::: "memory");
    };

    issue_tile(0, 0);
    issue_tile(1, 1);

    const int mat   = tid >> 6;          // 0:A(T.T^t) 1:B(S.S^t) 2:M(S.T^t)
    const int team  = (tid >> 5) & 1;
    const int patch = tid & 31;
    const int ii    = patch >> 3;        // 0..3 (row block of 8)
    const int jj    = patch & 7;         // 0..7 (col block of 4)

    unsigned long long acc2[32];
#pragma unroll
    for (int k = 0; k < 32; ++k) acc2[k] = 0ull;

#pragma unroll
    for (int k = 0; k < NT; ++k) {
        const int b = k & 1;
        if (k < NT - 1) { asm volatile("cp.async.wait_group 1;" ::: "memory"); }
        else            { asm volatile("cp.async.wait_group 0;" ::: "memory"); }
        __syncthreads();     // tile k resident in buf b

        // ---- Per-position inverse norms (64 threads; 4-way ILP chains) ----
        if (tid < 2 * TP) {
            const int half = tid >> 5;   // 0: S, 1: T
            const int p = tid & 31;
            const float* arr = half ? sT[b] : sS[b];
            float s0 = 0.f, s1 = 0.f, s2 = 0.f, s3 = 0.f;
#pragma unroll
            for (int r = 0; r < 8; ++r) {
                const float x0 = arr[(r     ) * PITCH + p];
                const float x1 = arr[(r +  8) * PITCH + p];
                const float x2 = arr[(r + 16) * PITCH + p];
                const float x3 = arr[(r + 24) * PITCH + p];
                s0 = fmaf(x0, x0, s0); s1 = fmaf(x1, x1, s1);
                s2 = fmaf(x2, x2, s2); s3 = fmaf(x3, x3, s3);
            }
            const float iv = 1.f / (sqrtf((s0 + s1) + (s2 + s3)) + 1e-8f);
            (half ? ivT[b] : ivS[b])[p] = iv;
        }
        __syncthreads();

        // ---- Normalize tile in place (float4) ----
#pragma unroll
        for (int s = tid; s < 512; s += TH1) {
            const int tensor = s >> 8;
            const int r = (s >> 3) & 31;         // physical row
            const int q = s & 7;
            float* arr = tensor ? sT[b] : sS[b];
            const float* iv = tensor ? ivT[b] : ivS[b];
            const float4 wv = *(const float4*)&iv[4 * q];
            float4 v = *(float4*)&arr[r * PITCH + 4 * q];
            v.x *= wv.x; v.y *= wv.y; v.z *= wv.z; v.w *= wv.w;
            *(float4*)&arr[r * PITCH + 4 * q] = v;
        }
        __syncthreads();

        // ---- Gram accumulation: 8x4 patches, f32x2 position pairs ----
        const float* __restrict__ Xi = (mat == 0) ? sT[b] : sS[b];
        const float* __restrict__ Xj = (mat == 1) ? sS[b] : sT[b];
        // sigma(8*ii+rr) = 8*(rr&3) + (rr>>2) + 2*ii ; sigma(4*jj+qq) = 8*qq + jj
        const float* xiB = Xi + 2 * ii * PITCH + 2 * team;
        const float* xjB = Xj + jj * PITCH     + 2 * team;

#pragma unroll
        for (int m = 0; m < TP / 4; ++m) {
            const int off = 4 * m;

            unsigned long long xj2[4];
#pragma unroll
            for (int qq = 0; qq < 4; ++qq)
                xj2[qq] = *(const unsigned long long*)&xjB[(8 * qq) * PITCH + off];

            unsigned long long xi2[8];
#pragma unroll
            for (int rr = 0; rr < 8; ++rr)
                xi2[rr] = *(const unsigned long long*)&xiB[(8 * (rr & 3) + (rr >> 2)) * PITCH + off];

#pragma unroll
            for (int rr = 0; rr < 8; ++rr)
#pragma unroll
                for (int qq = 0; qq < 4; ++qq)
                    asm("fma.rn.f32x2 %0, %1, %2, %0;"
                        : "+l"(acc2[rr * 4 + qq]) : "l"(xi2[rr]), "l"(xj2[qq]));
        }
        __syncthreads();                 // done reading buf b

        if (k + 2 < NT) issue_tile(b, k + 2);   // stream next tile into freed buffer
    }

    // ---- Fire-and-forget accumulation into replicated slot ----
    const int rep = w & (NREP - 1);
    float* dst = g_acc + ((size_t)(rep * NI + n) * 3 + mat) * 1024;
#pragma unroll
    for (int rr = 0; rr < 8; ++rr)
#pragma unroll
        for (int qq = 0; qq < 4; ++qq) {
            const float2 v = *(const float2*)&acc2[rr * 4 + qq];
            atomicAdd(&dst[(8 * ii + rr) * 32 + 4 * jj + qq], v.x + v.y);
        }
}

// 96 blocks x 256 threads: one thread per Gram element (8*3*1024 = 24576).
// Two replica loads, zero for next replay, weight, square, reduce, atomic out.
__global__ __launch_bounds__(256) void k_final(float* __restrict__ out) {
    const int t   = threadIdx.x;
    const int gid = blockIdx.x * 256 + t;             // 0..24575
    const int n   = gid / 3072;
    const int rem = gid % 3072;                       // mat*1024 + el
    const int mat = rem >> 10;

    const float v0 = g_acc[(size_t)(0 * NI + n) * 3072 + rem];
    const float v1 = g_acc[(size_t)(1 * NI + n) * 3072 + rem];
    g_acc[(size_t)(0 * NI + n) * 3072 + rem] = 0.f;
    g_acc[(size_t)(1 * NI + n) * 3072 + rem] = 0.f;
    const float v = v0 + v1;

    float contrib = (mat == 2) ? -2.f * v * v : v * v;

#pragma unroll
    for (int off = 16; off > 0; off >>= 1)
        contrib += __shfl_down_sync(0xffffffffu, contrib, off);

    __shared__ float wsum[8];
    if ((t & 31) == 0) wsum[t >> 5] = contrib;
    __syncthreads();

    if (t < 32) {
        float s = (t < 8) ? wsum[t] : 0.f;
#pragma unroll
        for (int off = 4; off > 0; off >>= 1)
            s += __shfl_down_sync(0xffffffffu, s, off);
        // loss = total / (HW^2) / (B*L)
        if (t == 0) atomicAdd(out, s * (1.f / (16777216.f * 8.f)));
    }
}

extern "C" void kernel_launch(void* const* d_in, const int* in_sizes, int n_in,
                              void* d_out, int out_size) {
    const float* S = (const float*)d_in[0];
    const float* T = (const float*)d_in[1];
    (void)in_sizes; (void)n_in; (void)out_size;

    dim3 g1(BPI, NI);
    k_partial<<<g1, TH1>>>(S, T, (float*)d_out);
    k_final<<<96, 256>>>((float*)d_out);
}

// round 13
// speedup vs baseline: 1.5443x; 1.5443x over previous
#include <cuda_runtime.h>
#include <math.h>

// Shapes fixed by reference: [2,4,32,64,64]
constexpr int Cc    = 32;          // channels per tensor
constexpr int HW    = 4096;        // 64*64 positions
constexpr int NI    = 8;           // B*L items
constexpr int TPB   = 128;         // positions per block
constexpr int BPI   = 32;          // blocks per item -> 256 blocks
constexpr int PITCH = 132;         // PITCH % 32 == 4 -> conflict-free fragments
constexpr int TH1   = 256;         // 8 warps
constexpr int NREP  = 2;           // accumulator replicas

// Replicated stacked-Gram accumulators: [replica][item][64*64].
// Zero at module load; k_final re-zeroes after reading (graph-replay clean).
__device__ float g_acc[(size_t)NREP * NI * 4096];

__global__ __launch_bounds__(TH1) void k_partial(const float* __restrict__ S,
                                                 const float* __restrict__ T,
                                                 float* __restrict__ out) {
    // Stacked normalized tile U[64][TPB]: rows 0-31 = T-hat, 32-63 = S-hat.
    __shared__ __align__(16) float sU[64 * PITCH];
    __shared__ __align__(16) float ivv[2][TPB];    // [0]: T norms, [1]: S norms

    const int n   = blockIdx.y;
    const int blk = blockIdx.x;
    const int tid = threadIdx.x;
    const int p0  = blk * TPB;

    if (blk == 0 && n == 0 && tid == 0) *out = 0.f;   // graph edge orders before k_final

    const float4* __restrict__ Sb4 = (const float4*)(S + (size_t)n * Cc * HW);
    const float4* __restrict__ Tb4 = (const float4*)(T + (size_t)n * Cc * HW);

    // ---- Load [2 x 32 x 128] f32 as float4 (coalesced) ----
#pragma unroll
    for (int s = tid; s < 2048; s += TH1) {
        const int tensor = s >> 10;          // 0: T -> rows 0-31, 1: S -> rows 32-63
        const int c = (s >> 5) & 31;
        const int q = s & 31;
        const float4 v = tensor ? Sb4[(size_t)c * (HW / 4) + (p0 >> 2) + q]
                                : Tb4[(size_t)c * (HW / 4) + (p0 >> 2) + q];
        *(float4*)&sU[(tensor * 32 + c) * PITCH + 4 * q] = v;
    }
    __syncthreads();

    // ---- Per-position inverse norms (one thread per (tensor, position)) ----
    {
        const int half = tid >> 7;           // 0: rows 0-31 (T), 1: rows 32-63 (S)
        const int p = tid & 127;
        const float* base = sU + half * 32 * PITCH;
        float s0 = 0.f, s1 = 0.f, s2 = 0.f, s3 = 0.f;
#pragma unroll
        for (int r = 0; r < 8; ++r) {
            const float x0 = base[(r     ) * PITCH + p];
            const float x1 = base[(r +  8) * PITCH + p];
            const float x2 = base[(r + 16) * PITCH + p];
            const float x3 = base[(r + 24) * PITCH + p];
            s0 = fmaf(x0, x0, s0); s1 = fmaf(x1, x1, s1);
            s2 = fmaf(x2, x2, s2); s3 = fmaf(x3, x3, s3);
        }
        ivv[half][p] = 1.f / (sqrtf((s0 + s1) + (s2 + s3)) + 1e-8f);
    }
    __syncthreads();

    // ---- Normalize and convert to tf32 in place ----
#pragma unroll
    for (int s = tid; s < 2048; s += TH1) {
        const int row = s >> 5;              // 0..63
        const int q = s & 31;
        const float4 w = *(const float4*)&ivv[row >> 5][4 * q];
        float4 v = *(float4*)&sU[row * PITCH + 4 * q];
        v.x *= w.x; v.y *= w.y; v.z *= w.z; v.w *= w.w;
        unsigned t0, t1, t2, t3;
        asm("cvt.rna.tf32.f32 %0, %1;" : "=r"(t0) : "f"(v.x));
        asm("cvt.rna.tf32.f32 %0, %1;" : "=r"(t1) : "f"(v.y));
        asm("cvt.rna.tf32.f32 %0, %1;" : "=r"(t2) : "f"(v.z));
        asm("cvt.rna.tf32.f32 %0, %1;" : "=r"(t3) : "f"(v.w));
        uint4 o = {t0, t1, t2, t3};
        *(uint4*)&sU[row * PITCH + 4 * q] = o;
    }
    __syncthreads();

    // ---- Tensor-core Gram: G = U * U^T, 64x64 via m16n8k8 tf32 ----
    // Warp w: row strip i0 = 16*(w&3); column half j0 = 32*(w>>2), 4 n-tiles of 8.
    const int wrp  = tid >> 5;
    const int lane = tid & 31;
    const int i0   = 16 * (wrp & 3);
    const int j0   = 32 * (wrp >> 2);
    const int gi   = lane >> 2;              // 0..7
    const int gk   = lane & 3;               // 0..3

    float acc[4][4];
#pragma unroll
    for (int t = 0; t < 4; ++t)
#pragma unroll
        for (int r = 0; r < 4; ++r) acc[t][r] = 0.f;

    const float* aR0 = sU + (i0 + gi) * PITCH + gk;        // A rows gi, gi+8
    const float* aR1 = aR0 + 8 * PITCH;

#pragma unroll
    for (int ks = 0; ks < TPB / 8; ++ks) {
        const int kk = 8 * ks;
        unsigned a0 = __float_as_uint(aR0[kk]);
        unsigned a1 = __float_as_uint(aR1[kk]);
        unsigned a2 = __float_as_uint(aR0[kk + 4]);
        unsigned a3 = __float_as_uint(aR1[kk + 4]);
#pragma unroll
        for (int nt = 0; nt < 4; ++nt) {
            const float* bB = sU + (j0 + 8 * nt + gi) * PITCH + gk;
            unsigned b0 = __float_as_uint(bB[kk]);
            unsigned b1 = __float_as_uint(bB[kk + 4]);
            asm("mma.sync.aligned.m16n8k8.row.col.f32.tf32.tf32.f32 "
                "{%0,%1,%2,%3}, {%4,%5,%6,%7}, {%8,%9}, {%0,%1,%2,%3};"
                : "+f"(acc[nt][0]), "+f"(acc[nt][1]), "+f"(acc[nt][2]), "+f"(acc[nt][3])
                : "r"(a0), "r"(a1), "r"(a2), "r"(a3), "r"(b0), "r"(b1));
        }
    }

    // ---- Fire-and-forget accumulation into replicated slot ----
    // D layout: reg r -> row = gi + (r>=2 ? 8 : 0), col = 2*gk + (r&1).
    const int rep = blk & (NREP - 1);
    float* dst = g_acc + (size_t)(rep * NI + n) * 4096;
#pragma unroll
    for (int nt = 0; nt < 4; ++nt) {
#pragma unroll
        for (int r = 0; r < 4; ++r) {
            const int i = i0 + gi + ((r >> 1) << 3);
            const int j = j0 + 8 * nt + 2 * gk + (r & 1);
            atomicAdd(&dst[i * 64 + j], acc[nt][r]);
        }
    }
}

// 64 blocks x 512 threads: one thread per Gram element (8 x 4096 = 32768).
// weight: +1 inside TT/SS diagonal blocks, -1 in TS/ST off-diagonal blocks.
__global__ __launch_bounds__(512) void k_final(float* __restrict__ out) {
    const int t   = threadIdx.x;
    const int gid = blockIdx.x * 512 + t;             // 0..32767
    const int n   = gid >> 12;
    const int idx = gid & 4095;                       // i*64 + j
    const int i   = idx >> 6, j = idx & 63;

    const float v0 = g_acc[(size_t)(0 * NI + n) * 4096 + idx];
    const float v1 = g_acc[(size_t)(1 * NI + n) * 4096 + idx];
    g_acc[(size_t)(0 * NI + n) * 4096 + idx] = 0.f;
    g_acc[(size_t)(1 * NI + n) * 4096 + idx] = 0.f;
    const float v = v0 + v1;

    const float w = (((i ^ j) & 32) == 0) ? 1.f : -1.f;
    float contrib = w * v * v;

#pragma unroll
    for (int off = 16; off > 0; off >>= 1)
        contrib += __shfl_down_sync(0xffffffffu, contrib, off);

    __shared__ float wsum[16];
    if ((t & 31) == 0) wsum[t >> 5] = contrib;
    __syncthreads();

    if (t < 32) {
        float s = (t < 16) ? wsum[t] : 0.f;
#pragma unroll
        for (int off = 8; off > 0; off >>= 1)
            s += __shfl_down_sync(0xffffffffu, s, off);
        // loss = total / (HW^2) / (B*L)
        if (t == 0) atomicAdd(out, s * (1.f / (16777216.f * 8.f)));
    }
}

extern "C" void kernel_launch(void* const* d_in, const int* in_sizes, int n_in,
                              void* d_out, int out_size) {
    const float* S = (const float*)d_in[0];
    const float* T = (const float*)d_in[1];
    (void)in_sizes; (void)n_in; (void)out_size;

    dim3 g1(BPI, NI);
    k_partial<<<g1, TH1>>>(S, T, (float*)d_out);
    k_final<<<64, 512>>>((float*)d_out);
}

// round 14
// speedup vs baseline: 1.5714x; 1.0175x over previous
#include <cuda_runtime.h>
#include <math.h>

// Shapes fixed by reference: [2,4,32,64,64]
constexpr int Cc    = 32;          // channels per tensor
constexpr int HW    = 4096;        // 64*64 positions
constexpr int NI    = 8;           // B*L items
constexpr int TPB   = 128;         // positions per block
constexpr int BPI   = 32;          // blocks per item -> 256 blocks
constexpr int PITCH = 132;         // PITCH % 32 == 4 -> conflict-free fragments
constexpr int TH1   = 256;         // 8 warps
constexpr int NREP  = 16;          // accumulator replicas (2 CTAs contend/address)

// Replicated stacked-Gram accumulators: [replica][item][64*64] = 2 MB.
// Zero at module load; k_final re-zeroes after reading (graph-replay clean).
__device__ float g_acc[(size_t)NREP * NI * 4096];

__global__ __launch_bounds__(TH1) void k_partial(const float* __restrict__ S,
                                                 const float* __restrict__ T,
                                                 float* __restrict__ out) {
    // Stacked normalized tile U[64][TPB]: rows 0-31 = T-hat, 32-63 = S-hat.
    __shared__ __align__(16) float sU[64 * PITCH];
    __shared__ __align__(16) float ivv[2][TPB];    // [0]: T norms, [1]: S norms

    const int n   = blockIdx.y;
    const int blk = blockIdx.x;
    const int tid = threadIdx.x;
    const int p0  = blk * TPB;

    if (blk == 0 && n == 0 && tid == 0) *out = 0.f;   // graph edge orders before k_final

    const float4* __restrict__ Sb4 = (const float4*)(S + (size_t)n * Cc * HW);
    const float4* __restrict__ Tb4 = (const float4*)(T + (size_t)n * Cc * HW);

    // ---- Load [2 x 32 x 128] f32 as float4 (coalesced) ----
#pragma unroll
    for (int s = tid; s < 2048; s += TH1) {
        const int tensor = s >> 10;          // 0: T -> rows 0-31, 1: S -> rows 32-63
        const int c = (s >> 5) & 31;
        const int q = s & 31;
        const float4 v = tensor ? Sb4[(size_t)c * (HW / 4) + (p0 >> 2) + q]
                                : Tb4[(size_t)c * (HW / 4) + (p0 >> 2) + q];
        *(float4*)&sU[(tensor * 32 + c) * PITCH + 4 * q] = v;
    }
    __syncthreads();

    // ---- Per-position inverse norms (one thread per (tensor, position)) ----
    {
        const int half = tid >> 7;           // 0: rows 0-31 (T), 1: rows 32-63 (S)
        const int p = tid & 127;
        const float* base = sU + half * 32 * PITCH;
        float s0 = 0.f, s1 = 0.f, s2 = 0.f, s3 = 0.f;
#pragma unroll
        for (int r = 0; r < 8; ++r) {
            const float x0 = base[(r     ) * PITCH + p];
            const float x1 = base[(r +  8) * PITCH + p];
            const float x2 = base[(r + 16) * PITCH + p];
            const float x3 = base[(r + 24) * PITCH + p];
            s0 = fmaf(x0, x0, s0); s1 = fmaf(x1, x1, s1);
            s2 = fmaf(x2, x2, s2); s3 = fmaf(x3, x3, s3);
        }
        ivv[half][p] = 1.f / (sqrtf((s0 + s1) + (s2 + s3)) + 1e-8f);
    }
    __syncthreads();

    // ---- Normalize and convert to tf32 in place ----
#pragma unroll
    for (int s = tid; s < 2048; s += TH1) {
        const int row = s >> 5;              // 0..63
        const int q = s & 31;
        const float4 w = *(const float4*)&ivv[row >> 5][4 * q];
        float4 v = *(float4*)&sU[row * PITCH + 4 * q];
        v.x *= w.x; v.y *= w.y; v.z *= w.z; v.w *= w.w;
        unsigned t0, t1, t2, t3;
        asm("cvt.rna.tf32.f32 %0, %1;" : "=r"(t0) : "f"(v.x));
        asm("cvt.rna.tf32.f32 %0, %1;" : "=r"(t1) : "f"(v.y));
        asm("cvt.rna.tf32.f32 %0, %1;" : "=r"(t2) : "f"(v.z));
        asm("cvt.rna.tf32.f32 %0, %1;" : "=r"(t3) : "f"(v.w));
        uint4 o = {t0, t1, t2, t3};
        *(uint4*)&sU[row * PITCH + 4 * q] = o;
    }
    __syncthreads();

    // ---- Tensor-core Gram: G = U * U^T, 64x64 via m16n8k8 tf32 ----
    // Warp w: row strip i0 = 16*(w&3); column half j0 = 32*(w>>2), 4 n-tiles of 8.
    const int wrp  = tid >> 5;
    const int lane = tid & 31;
    const int i0   = 16 * (wrp & 3);
    const int j0   = 32 * (wrp >> 2);
    const int gi   = lane >> 2;              // 0..7
    const int gk   = lane & 3;               // 0..3

    float acc[4][4];
#pragma unroll
    for (int t = 0; t < 4; ++t)
#pragma unroll
        for (int r = 0; r < 4; ++r) acc[t][r] = 0.f;

    const float* aR0 = sU + (i0 + gi) * PITCH + gk;        // A rows gi, gi+8
    const float* aR1 = aR0 + 8 * PITCH;

#pragma unroll
    for (int ks = 0; ks < TPB / 8; ++ks) {
        const int kk = 8 * ks;
        unsigned a0 = __float_as_uint(aR0[kk]);
        unsigned a1 = __float_as_uint(aR1[kk]);
        unsigned a2 = __float_as_uint(aR0[kk + 4]);
        unsigned a3 = __float_as_uint(aR1[kk + 4]);
#pragma unroll
        for (int nt = 0; nt < 4; ++nt) {
            const float* bB = sU + (j0 + 8 * nt + gi) * PITCH + gk;
            unsigned b0 = __float_as_uint(bB[kk]);
            unsigned b1 = __float_as_uint(bB[kk + 4]);
            asm("mma.sync.aligned.m16n8k8.row.col.f32.tf32.tf32.f32 "
                "{%0,%1,%2,%3}, {%4,%5,%6,%7}, {%8,%9}, {%0,%1,%2,%3};"
                : "+f"(acc[nt][0]), "+f"(acc[nt][1]), "+f"(acc[nt][2]), "+f"(acc[nt][3])
                : "r"(a0), "r"(a1), "r"(a2), "r"(a3), "r"(b0), "r"(b1));
        }
    }

    // ---- Fire-and-forget v2 reductions into replicated slot ----
    // D layout: regs (0,1) -> row gi,   cols 2*gk, 2*gk+1 (contiguous)
    //           regs (2,3) -> row gi+8, cols 2*gk, 2*gk+1
    const int rep = blk & (NREP - 1);
    float* dst = g_acc + (size_t)(rep * NI + n) * 4096;
#pragma unroll
    for (int nt = 0; nt < 4; ++nt) {
        const int jcol = j0 + 8 * nt + 2 * gk;
        float* d0 = &dst[(i0 + gi    ) * 64 + jcol];
        float* d1 = &dst[(i0 + gi + 8) * 64 + jcol];
        asm volatile("red.global.add.v2.f32 [%0], {%1,%2};"
                     :: "l"(d0), "f"(acc[nt][0]), "f"(acc[nt][1]) : "memory");
        asm volatile("red.global.add.v2.f32 [%0], {%1,%2};"
                     :: "l"(d1), "f"(acc[nt][2]), "f"(acc[nt][3]) : "memory");
    }
}

// 32 blocks x 1024 threads: one thread per Gram element (8 x 4096 = 32768).
// Sum 16 replicas (L2-hot, coalesced), zero them, weight (+1 diag blocks,
// -1 cross blocks), square, reduce, atomic out.
__global__ __launch_bounds__(1024) void k_final(float* __restrict__ out) {
    const int t   = threadIdx.x;
    const int gid = blockIdx.x * 1024 + t;            // 0..32767
    const int n   = gid >> 12;
    const int idx = gid & 4095;                       // i*64 + j
    const int i   = idx >> 6, j = idx & 63;

    float v = 0.f;
#pragma unroll
    for (int r = 0; r < NREP; ++r)
        v += g_acc[(size_t)(r * NI + n) * 4096 + idx];
#pragma unroll
    for (int r = 0; r < NREP; ++r)
        g_acc[(size_t)(r * NI + n) * 4096 + idx] = 0.f;

    const float w = (((i ^ j) & 32) == 0) ? 1.f : -1.f;
    float contrib = w * v * v;

#pragma unroll
    for (int off = 16; off > 0; off >>= 1)
        contrib += __shfl_down_sync(0xffffffffu, contrib, off);

    __shared__ float wsum[32];
    if ((t & 31) == 0) wsum[t >> 5] = contrib;
    __syncthreads();

    if (t < 32) {
        float s = wsum[t];
#pragma unroll
        for (int off = 16; off > 0; off >>= 1)
            s += __shfl_down_sync(0xffffffffu, s, off);
        // loss = total / (HW^2) / (B*L)
        if (t == 0) atomicAdd(out, s * (1.f / (16777216.f * 8.f)));
    }
}

extern "C" void kernel_launch(void* const* d_in, const int* in_sizes, int n_in,
                              void* d_out, int out_size) {
    const float* S = (const float*)d_in[0];
    const float* T = (const float*)d_in[1];
    (void)in_sizes; (void)n_in; (void)out_size;

    dim3 g1(BPI, NI);
    k_partial<<<g1, TH1>>>(S, T, (float*)d_out);
    k_final<<<32, 1024>>>((float*)d_out);
}